// round 4
// baseline (speedup 1.0000x reference)
#include <cuda_runtime.h>

// FWHT of 4096-wide rows, sign flip + 2^-6 normalization. Single kernel.
// 256 threads/CTA, 1 row/CTA, 16 fp32/thread, three register-H16 rounds,
// two shared exchanges (one side vectorized each), all global accesses
// perfectly coalesced, all shared accesses bank-conflict-free with
// immediate offsets.
//
// Bit plan (i = element index, t = thread, 12 bits total):
//   Round 1: i = g*1024 + t*4 + c   regs {1,0,11,10} -> strides 1,2,1024,2048
//   Round 2: i[5:2]=j (regs), i[1:0]=t[1:0], i[9:6]=t[5:2], i[11:10]=t[7:6]
//                                   -> strides 4,8,16,32
//   Round 3: i[9:6]=k (regs), i[5:0]=t[5:0], i[11:10]=t[7:6]
//                                   -> strides 64,128,256,512
//
// Exchange 1: rows keyed by round-2 reader, pitch 20 (conflict-free both
//   sides; writer scalar STS imm, reader 4x LDS.128).
// Exchange 2: rows keyed by round-2 writer, pitch 24, quad slots XOR'd by
//   (t&4) to kill the pitch-24 lane-pair bank collisions; writer 4x STS.128,
//   reader scalar LDS with two bases (B and B^4 for odd k).

#define FWHT_D 4096

__device__ __forceinline__ void h16(float (&r)[16])
{
    #pragma unroll
    for (int p = 1; p < 16; p <<= 1) {
        #pragma unroll
        for (int k = 0; k < 16; ++k) {
            if ((k & p) == 0) {
                const float a = r[k];
                const float b = r[k | p];
                r[k]     = a + b;
                r[k | p] = a - b;
            }
        }
    }
}

__global__ __launch_bounds__(256) void RHTRotation_82394652607202_kernel(
    const float* __restrict__ x,
    const float* __restrict__ signs,
    float* __restrict__ out)
{
    __shared__ float sm[6144];            // 24 KB, reused by both exchanges

    const int t = threadIdx.x;            // 0..255
    const long long rowoff = (long long)blockIdx.x * FWHT_D;
    const float* xr = x + rowoff;

    float r[16];

    // ---- load x and signs: i = g*1024 + t*4 + c, 512B contiguous per warp-instr ----
    float4 xv[4], sv[4];
    #pragma unroll
    for (int g = 0; g < 4; ++g)
        xv[g] = *reinterpret_cast<const float4*>(xr + g * 1024 + t * 4);
    #pragma unroll
    for (int g = 0; g < 4; ++g)
        sv[g] = *reinterpret_cast<const float4*>(signs + g * 1024 + t * 4);

    const float scale = 0.015625f;        // 4096^-0.5 exact
    #pragma unroll
    for (int g = 0; g < 4; ++g) {
        r[g * 4 + 0] = xv[g].x * (sv[g].x * scale);
        r[g * 4 + 1] = xv[g].y * (sv[g].y * scale);
        r[g * 4 + 2] = xv[g].z * (sv[g].z * scale);
        r[g * 4 + 3] = xv[g].w * (sv[g].w * scale);
    }

    // ---- round 1: strides 1,2,1024,2048 (reg bits c0,c1,g0,g1) ----
    h16(r);

    // ---- exchange 1 write: value (g,c) -> row ((g<<6)|((t>>4)<<2)|c), col t&15, pitch 20
    //      addr = g*1280 + (t>>4)*80 + c*20 + (t&15)   (imm in g,c) ----
    {
        const int base = (t >> 4) * 80 + (t & 15);
        #pragma unroll
        for (int g = 0; g < 4; ++g)
            #pragma unroll
            for (int c = 0; c < 4; ++c)
                sm[base + g * 1280 + c * 20] = r[g * 4 + c];
    }
    __syncthreads();

    // ---- exchange 1 read: row t, cols 0..15 -> 4x LDS.128 ----
    {
        const float* rp = sm + t * 20;
        #pragma unroll
        for (int q = 0; q < 4; ++q) {
            const float4 v = *reinterpret_cast<const float4*>(rp + 4 * q);
            r[q * 4 + 0] = v.x; r[q * 4 + 1] = v.y;
            r[q * 4 + 2] = v.z; r[q * 4 + 3] = v.w;
        }
    }

    // ---- round 2: strides 4,8,16,32 (regs j = i[5:2]) ----
    h16(r);

    __syncthreads();                      // buffer reuse: all reads done before rewrite

    // ---- exchange 2 write: row t, pitch 24, quad q at slot (4q ^ (t&4)) -> 4x STS.128 ----
    {
        const int c4 = t & 4;
        float* wp = sm + t * 24;
        #pragma unroll
        for (int q = 0; q < 4; ++q) {
            *reinterpret_cast<float4*>(wp + ((4 * q) ^ c4)) =
                make_float4(r[q * 4 + 0], r[q * 4 + 1], r[q * 4 + 2], r[q * 4 + 3]);
        }
    }
    __syncthreads();

    // ---- exchange 2 read: value k at row ((t>>6)<<6 | k<<2 | (t&3)),
    //      slot ((t>>2)&15) ^ (4*(k&1));  addr = A + k*96 + (B or B^4) ----
    {
        const int A  = (t >> 6) * 1536 + (t & 3) * 24;
        const int B  = (t >> 2) & 15;
        const int be = A + B;
        const int bo = A + (B ^ 4);
        #pragma unroll
        for (int k = 0; k < 16; ++k)
            r[k] = sm[((k & 1) ? bo : be) + k * 96];
    }

    // ---- round 3: strides 64,128,256,512 (regs k = i[9:6]) ----
    h16(r);

    // ---- store: i = (t>>6)<<10 | k<<6 | (t&63): 128B contiguous per warp-instr, imm ----
    {
        float* op = out + rowoff + (t >> 6) * 1024 + (t & 63);
        #pragma unroll
        for (int k = 0; k < 16; ++k)
            op[k * 64] = r[k];
    }
}

extern "C" void kernel_launch(void* const* d_in, const int* in_sizes, int n_in,
                              void* d_out, int out_size)
{
    const float* a = (const float*)d_in[0];
    const float* b = (const float*)d_in[1];
    const float* x;
    const float* signs;
    if (in_sizes[0] == FWHT_D && in_sizes[1] > FWHT_D) { signs = a; x = b; }
    else                                               { x = a; signs = b; }

    const int rows = out_size / FWHT_D;
    RHTRotation_82394652607202_kernel<<<rows, 256>>>(x, signs, (float*)d_out);
}

// round 5
// speedup vs baseline: 1.1337x; 1.1337x over previous
#include <cuda_runtime.h>
#include <cstdint>

// FWHT of 4096-wide rows, sign flip + 2^-6 normalization. Single kernel.
// Row input is fetched by cp.async.bulk (TMA 1D) into shared memory — the
// DMA engine keeps whole rows in flight, removing the per-warp LDG
// scoreboard/MLP ceiling that capped DRAM read bandwidth at ~4.5 TB/s.
//
// 256 threads/CTA, 1 row/CTA, 16 fp32/thread, three register-H16 rounds,
// two shared exchanges (same verified structure as round 4):
//   Round 1: i = g*1024 + t*4 + c   regs {1,0,11,10} -> strides 1,2,1024,2048
//   Round 2: regs j = i[5:2]                         -> strides 4,8,16,32
//   Round 3: regs k = i[9:6]                         -> strides 64..512
// Exchange 1: pitch-20 rows keyed by reader (scalar STS imm / 4x LDS.128).
// Exchange 2: pitch-24 rows keyed by writer, quad slots XOR (t&4)
//             (4x STS.128 / scalar LDS imm, two bases).

#define FWHT_D 4096

__device__ __forceinline__ uint32_t smem_u32(const void* p)
{
    uint32_t a;
    asm("{ .reg .u64 tmp; cvta.to.shared.u64 tmp, %1; cvt.u32.u64 %0, tmp; }"
        : "=r"(a) : "l"(p));
    return a;
}

__device__ __forceinline__ void h16(float (&r)[16])
{
    #pragma unroll
    for (int p = 1; p < 16; p <<= 1) {
        #pragma unroll
        for (int k = 0; k < 16; ++k) {
            if ((k & p) == 0) {
                const float a = r[k];
                const float b = r[k | p];
                r[k]     = a + b;
                r[k | p] = a - b;
            }
        }
    }
}

__global__ __launch_bounds__(256) void RHTRotation_82394652607202_kernel(
    const float* __restrict__ x,
    const float* __restrict__ signs,
    float* __restrict__ out)
{
    __shared__ __align__(128) float in_buf[FWHT_D];   // 16 KB TMA landing
    __shared__ __align__(128) float ex[6144];         // 24 KB exchange buffer
    __shared__ __align__(8)   uint64_t mbar;

    const int t = threadIdx.x;                         // 0..255
    const long long rowoff = (long long)blockIdx.x * FWHT_D;

    const uint32_t mb = smem_u32(&mbar);

    // ---- init mbarrier, then launch the bulk copy of this row ----
    if (t == 0) {
        asm volatile("mbarrier.init.shared.b64 [%0], %1;" :: "r"(mb), "r"(1));
        asm volatile("fence.proxy.async.shared::cta;" ::: "memory");
    }
    __syncthreads();
    if (t == 0) {
        asm volatile("mbarrier.arrive.expect_tx.shared.b64 _, [%0], %1;"
                     :: "r"(mb), "r"((unsigned)(FWHT_D * 4)) : "memory");
        asm volatile(
            "cp.async.bulk.shared::cta.global.mbarrier::complete_tx::bytes "
            "[%0], [%1], %2, [%3];"
            :: "r"(smem_u32(in_buf)), "l"(x + rowoff),
               "r"((unsigned)(FWHT_D * 4)), "r"(mb)
            : "memory");
    }

    // ---- overlap: fetch signs (L2-resident) while the DMA runs ----
    float4 sv[4];
    #pragma unroll
    for (int g = 0; g < 4; ++g)
        sv[g] = *reinterpret_cast<const float4*>(signs + g * 1024 + t * 4);

    // ---- wait for the row (acquire orders the smem reads below) ----
    {
        uint32_t done;
        asm volatile(
            "{\n\t.reg .pred p;\n\t"
            "mbarrier.try_wait.parity.acquire.cta.shared::cta.b64 p, [%1], 0;\n\t"
            "selp.b32 %0, 1, 0, p;\n\t}"
            : "=r"(done) : "r"(mb) : "memory");
        if (!done) {
            asm volatile(
                "{\n\t.reg .pred P1;\n\t"
                "WL_%=:\n\t"
                "mbarrier.try_wait.parity.acquire.cta.shared::cta.b64 P1, [%0], 0, 0x989680;\n\t"
                "@P1 bra.uni WD_%=;\n\t"
                "bra.uni WL_%=;\n\t"
                "WD_%=:\n\t}"
                :: "r"(mb) : "memory");
        }
    }

    float r[16];
    const float scale = 0.015625f;        // 4096^-0.5 exact

    // ---- round-1 gather from linear smem: 4x LDS.128, conflict-free ----
    #pragma unroll
    for (int g = 0; g < 4; ++g) {
        const float4 v = *reinterpret_cast<const float4*>(in_buf + g * 1024 + t * 4);
        r[g * 4 + 0] = v.x * (sv[g].x * scale);
        r[g * 4 + 1] = v.y * (sv[g].y * scale);
        r[g * 4 + 2] = v.z * (sv[g].z * scale);
        r[g * 4 + 3] = v.w * (sv[g].w * scale);
    }

    // ---- round 1: strides 1,2,1024,2048 ----
    h16(r);

    // ---- exchange 1 write: addr = g*1280 + (t>>4)*80 + c*20 + (t&15) ----
    {
        const int base = (t >> 4) * 80 + (t & 15);
        #pragma unroll
        for (int g = 0; g < 4; ++g)
            #pragma unroll
            for (int c = 0; c < 4; ++c)
                ex[base + g * 1280 + c * 20] = r[g * 4 + c];
    }
    __syncthreads();

    // ---- exchange 1 read: row t, 4x LDS.128 ----
    {
        const float* rp = ex + t * 20;
        #pragma unroll
        for (int q = 0; q < 4; ++q) {
            const float4 v = *reinterpret_cast<const float4*>(rp + 4 * q);
            r[q * 4 + 0] = v.x; r[q * 4 + 1] = v.y;
            r[q * 4 + 2] = v.z; r[q * 4 + 3] = v.w;
        }
    }

    // ---- round 2: strides 4,8,16,32 ----
    h16(r);

    __syncthreads();

    // ---- exchange 2 write: row t, pitch 24, quad slot (4q ^ (t&4)) ----
    {
        const int c4 = t & 4;
        float* wp = ex + t * 24;
        #pragma unroll
        for (int q = 0; q < 4; ++q) {
            *reinterpret_cast<float4*>(wp + ((4 * q) ^ c4)) =
                make_float4(r[q * 4 + 0], r[q * 4 + 1], r[q * 4 + 2], r[q * 4 + 3]);
        }
    }
    __syncthreads();

    // ---- exchange 2 read: addr = A + k*96 + (B or B^4) ----
    {
        const int A  = (t >> 6) * 1536 + (t & 3) * 24;
        const int B  = (t >> 2) & 15;
        const int be = A + B;
        const int bo = A + (B ^ 4);
        #pragma unroll
        for (int k = 0; k < 16; ++k)
            r[k] = ex[((k & 1) ? bo : be) + k * 96];
    }

    // ---- round 3: strides 64,128,256,512 ----
    h16(r);

    // ---- store: i = (t>>6)*1024 + k*64 + (t&63), 128B/instr, imm offsets ----
    {
        float* op = out + rowoff + (t >> 6) * 1024 + (t & 63);
        #pragma unroll
        for (int k = 0; k < 16; ++k)
            op[k * 64] = r[k];
    }
}

extern "C" void kernel_launch(void* const* d_in, const int* in_sizes, int n_in,
                              void* d_out, int out_size)
{
    const float* a = (const float*)d_in[0];
    const float* b = (const float*)d_in[1];
    const float* x;
    const float* signs;
    if (in_sizes[0] == FWHT_D && in_sizes[1] > FWHT_D) { signs = a; x = b; }
    else                                               { x = a; signs = b; }

    const int rows = out_size / FWHT_D;
    RHTRotation_82394652607202_kernel<<<rows, 256>>>(x, signs, (float*)d_out);
}